// round 1
// baseline (speedup 1.0000x reference)
#include <cuda_runtime.h>
#include <math.h>

// Problem constants (verified against reference at launch via in_sizes).
#define MAXN 100000
#define MAXE 800000
#define DDIM 128

// ---------------- device scratch (static __device__ arrays; no allocs) ----
__device__ float g_t1[MAXN * 128];   // mlp hidden 1 (uses first N*64 or N*128)
__device__ float g_t2[MAXN * 128];   // mlp hidden 2
__device__ float g_h0[MAXN * 128];   // prep mlp output
__device__ float g_q [MAXN * 128];
__device__ float g_k [MAXN * 128];
__device__ float g_v [MAXN * 128];
__device__ float g_sk[MAXN * 128];   // skip projection
__device__ float g_h1[MAXN * 128];   // conv output (agg + skip)
__device__ int   g_cnt[MAXN];
__device__ int   g_off[MAXN + 1];
__device__ int   g_bsum[256];
__device__ int   g_pos[MAXE];
__device__ int   g_esrc[MAXE];

// ---------------- SGEMM: C[M,Nc] = act(A[M,K] @ W[K,Nc] + bias (+ resid)) --
#define BM 64
#define BN 64
#define BKK 16
#define TM 4
#define TN 4
// 256 threads per block

__global__ void sgemm_bias(const float* __restrict__ A,
                           const float* __restrict__ W,
                           const float* __restrict__ bias,
                           float* __restrict__ C,
                           const float* __restrict__ resid,
                           int M, int K, int Nc, int do_relu)
{
    __shared__ float As[BKK][BM + 1];
    __shared__ float Bs[BKK][BN];

    const int t   = threadIdx.x;
    const int tx  = t & 15;       // 0..15 -> col groups of 4
    const int ty  = t >> 4;       // 0..15 -> row groups of 4
    const int row0 = blockIdx.y * BM;
    const int col0 = blockIdx.x * BN;

    float acc[TM][TN];
#pragma unroll
    for (int i = 0; i < TM; i++)
#pragma unroll
        for (int j = 0; j < TN; j++) acc[i][j] = 0.f;

    for (int k0 = 0; k0 < K; k0 += BKK) {
        // Load A tile (BM x BKK), store transposed As[k][m]
#pragma unroll
        for (int i = 0; i < 4; i++) {
            int idx = t + i * 256;          // 0..1023
            int r = idx >> 4;               // 0..63
            int c = idx & 15;               // 0..15
            int gr = row0 + r, gc = k0 + c;
            float val = 0.f;
            if (gr < M && gc < K) val = A[(long)gr * K + gc];
            As[c][r] = val;
        }
        // Load B tile (BKK x BN)
#pragma unroll
        for (int i = 0; i < 4; i++) {
            int idx = t + i * 256;
            int r = idx >> 6;               // 0..15
            int c = idx & 63;               // 0..63
            int gk = k0 + r;
            float val = 0.f;
            if (gk < K) val = W[(long)gk * Nc + col0 + c];
            Bs[r][c] = val;
        }
        __syncthreads();

#pragma unroll
        for (int k = 0; k < BKK; k++) {
            float a[TM], b[TN];
#pragma unroll
            for (int i = 0; i < TM; i++) a[i] = As[k][ty * TM + i];
#pragma unroll
            for (int j = 0; j < TN; j++) b[j] = Bs[k][tx * TN + j];
#pragma unroll
            for (int i = 0; i < TM; i++)
#pragma unroll
                for (int j = 0; j < TN; j++)
                    acc[i][j] += a[i] * b[j];
        }
        __syncthreads();
    }

#pragma unroll
    for (int i = 0; i < TM; i++) {
        int gr = row0 + ty * TM + i;
        if (gr >= M) continue;
#pragma unroll
        for (int j = 0; j < TN; j++) {
            int gc = col0 + tx * TN + j;
            float val = acc[i][j] + bias[gc];
            if (resid) val += resid[(long)gr * Nc + gc];
            if (do_relu) val = fmaxf(val, 0.f);
            C[(long)gr * Nc + gc] = val;
        }
    }
}

// ---------------- CSR build ------------------------------------------------
__global__ void zero_cnt_kernel(int N)
{
    int i = blockIdx.x * blockDim.x + threadIdx.x;
    if (i < N) g_cnt[i] = 0;
}

__global__ void hist_kernel(const int* __restrict__ dst, int E)
{
    int e = blockIdx.x * blockDim.x + threadIdx.x;
    if (e < E) g_pos[e] = atomicAdd(&g_cnt[dst[e]], 1);
}

__global__ void scan1_kernel(int N)
{
    __shared__ int sh[1024];
    int i = blockIdx.x * 1024 + threadIdx.x;
    int v = (i < N) ? g_cnt[i] : 0;
    sh[threadIdx.x] = v;
    __syncthreads();
    for (int d = 1; d < 1024; d <<= 1) {
        int tmp = (threadIdx.x >= d) ? sh[threadIdx.x - d] : 0;
        __syncthreads();
        sh[threadIdx.x] += tmp;
        __syncthreads();
    }
    if (i < N) g_off[i] = sh[threadIdx.x] - v;       // block-local exclusive
    if (threadIdx.x == 1023) g_bsum[blockIdx.x] = sh[1023];
}

__global__ void scan2_kernel(int nb)
{
    if (blockIdx.x == 0 && threadIdx.x == 0) {
        int run = 0;
        for (int i = 0; i < nb; i++) { int v = g_bsum[i]; g_bsum[i] = run; run += v; }
    }
}

__global__ void scan3_kernel(int N, int E)
{
    int i = blockIdx.x * blockDim.x + threadIdx.x;
    if (i < N) g_off[i] += g_bsum[i >> 10];
    if (i == 0) g_off[N] = E;
}

__global__ void scatter_kernel(const int* __restrict__ src,
                               const int* __restrict__ dst, int E)
{
    int e = blockIdx.x * blockDim.x + threadIdx.x;
    if (e < E) g_esrc[g_off[dst[e]] + g_pos[e]] = src[e];
}

// ---------------- attention: one warp per destination node -----------------
// q/k/v rows viewed as 32 float4s: lane L owns dims [4L, 4L+4); head = L/8.
// Per-head score = 8-lane group reduction of per-lane float4 dot.
__global__ void attn_kernel(int N)
{
    int gtid = blockIdx.x * blockDim.x + threadIdx.x;
    int n    = gtid >> 5;
    int lane = threadIdx.x & 31;
    if (n >= N) return;

    const float4* q4 = reinterpret_cast<const float4*>(g_q);
    const float4* k4 = reinterpret_cast<const float4*>(g_k);
    const float4* v4 = reinterpret_cast<const float4*>(g_v);
    const float4* s4 = reinterpret_cast<const float4*>(g_sk);
    float4*       o4 = reinterpret_cast<float4*>(g_h1);

    float4 ql = q4[(long)n * 32 + lane];
    int e0 = g_off[n], e1 = g_off[n + 1];

    const float NEG_INF = __int_as_float(0xff800000);
    const float scale = 0.17677669529663687f;  // 1/sqrt(32)
    float m = NEG_INF, s = 0.f;
    float4 acc = make_float4(0.f, 0.f, 0.f, 0.f);

    for (int e = e0; e < e1; e++) {
        int src = g_esrc[e];
        float4 kl = k4[(long)src * 32 + lane];
        float4 vl = v4[(long)src * 32 + lane];
        float p = ql.x * kl.x + ql.y * kl.y + ql.z * kl.z + ql.w * kl.w;
        p += __shfl_xor_sync(0xffffffffu, p, 1);
        p += __shfl_xor_sync(0xffffffffu, p, 2);
        p += __shfl_xor_sync(0xffffffffu, p, 4);
        float c = p * scale;                    // identical across 8-lane group
        float nm = fmaxf(m, c);
        float f = __expf(m - nm);               // -inf -> 0 on first edge
        float w = __expf(c - nm);
        s = s * f + w;
        acc.x = acc.x * f + w * vl.x;
        acc.y = acc.y * f + w * vl.y;
        acc.z = acc.z * f + w * vl.z;
        acc.w = acc.w * f + w * vl.w;
        m = nm;
    }
    float inv = (s > 0.f) ? (1.f / s) : 0.f;    // isolated node -> agg = 0
    float4 sk = s4[(long)n * 32 + lane];
    float4 o;
    o.x = acc.x * inv + sk.x;
    o.y = acc.y * inv + sk.y;
    o.z = acc.z * inv + sk.z;
    o.w = acc.w * inv + sk.w;
    o4[(long)n * 32 + lane] = o;
}

// ---------------- host side -------------------------------------------------
static void launch_gemm(const float* A, const float* W, const float* b,
                        float* C, const float* resid,
                        int M, int K, int Nc, int relu)
{
    dim3 grid(Nc / BN, (M + BM - 1) / BM);
    sgemm_bias<<<grid, 256>>>(A, W, b, C, resid, M, K, Nc, relu);
}

extern "C" void kernel_launch(void* const* d_in, const int* in_sizes, int n_in,
                              void* d_out, int out_size)
{
    const float* x    = (const float*)d_in[0];
    const int*   ei   = (const int*)  d_in[1];
    const float* pW1  = (const float*)d_in[2];
    const float* pb1  = (const float*)d_in[3];
    const float* pW2  = (const float*)d_in[4];
    const float* pb2  = (const float*)d_in[5];
    const float* pW3  = (const float*)d_in[6];
    const float* pb3  = (const float*)d_in[7];
    const float* uW1  = (const float*)d_in[8];
    const float* ub1  = (const float*)d_in[9];
    const float* uW2  = (const float*)d_in[10];
    const float* ub2  = (const float*)d_in[11];
    const float* uW3  = (const float*)d_in[12];
    const float* ub3  = (const float*)d_in[13];
    const float* qW   = (const float*)d_in[14];
    const float* qb   = (const float*)d_in[15];
    const float* kW   = (const float*)d_in[16];
    const float* kb   = (const float*)d_in[17];
    const float* vW   = (const float*)d_in[18];
    const float* vb   = (const float*)d_in[19];
    const float* sW   = (const float*)d_in[20];
    const float* sb   = (const float*)d_in[21];
    float* out = (float*)d_out;

    const int F = 5;
    const int N = in_sizes[0] / F;
    const int E = in_sizes[1] / 2;
    const int* src = ei;
    const int* dst = ei + E;

    float *t1, *t2, *h0, *qd, *kd, *vd, *skd, *h1;
    cudaGetSymbolAddress((void**)&t1,  g_t1);
    cudaGetSymbolAddress((void**)&t2,  g_t2);
    cudaGetSymbolAddress((void**)&h0,  g_h0);
    cudaGetSymbolAddress((void**)&qd,  g_q);
    cudaGetSymbolAddress((void**)&kd,  g_k);
    cudaGetSymbolAddress((void**)&vd,  g_v);
    cudaGetSymbolAddress((void**)&skd, g_sk);
    cudaGetSymbolAddress((void**)&h1,  g_h1);

    // 1) prep MLP: x(5) -> 64 relu -> 128 relu -> 128
    launch_gemm(x,  pW1, pb1, t1, nullptr, N, F,   64,  1);
    launch_gemm(t1, pW2, pb2, t2, nullptr, N, 64,  128, 1);
    launch_gemm(t2, pW3, pb3, h0, nullptr, N, 128, 128, 0);

    // 2) q, k, v, skip projections
    launch_gemm(h0, qW, qb, qd,  nullptr, N, 128, 128, 0);
    launch_gemm(h0, kW, kb, kd,  nullptr, N, 128, 128, 0);
    launch_gemm(h0, vW, vb, vd,  nullptr, N, 128, 128, 0);
    launch_gemm(h0, sW, sb, skd, nullptr, N, 128, 128, 0);

    // 3) CSR build by destination node
    int nb1024 = (N + 1023) / 1024;
    zero_cnt_kernel<<<(N + 255) / 256, 256>>>(N);
    hist_kernel<<<(E + 255) / 256, 256>>>(dst, E);
    scan1_kernel<<<nb1024, 1024>>>(N);
    scan2_kernel<<<1, 32>>>(nb1024);
    scan3_kernel<<<(N + 255) / 256, 256>>>(N, E);
    scatter_kernel<<<(E + 255) / 256, 256>>>(src, dst, E);

    // 4) attention (warp per node) -> h1 = agg + skip
    long threads_total = (long)N * 32;
    attn_kernel<<<(int)((threads_total + 255) / 256), 256>>>(N);

    // 5) update MLP with residual: out = h1 + mlp(h1)
    launch_gemm(h1, uW1, ub1, t1, nullptr, N, 128, 64,  1);
    launch_gemm(t1, uW2, ub2, t2, nullptr, N, 64,  128, 1);
    launch_gemm(t2, uW3, ub3, out, h1,     N, 128, 128, 0);
}

// round 4
// speedup vs baseline: 1.4709x; 1.4709x over previous
#include <cuda_runtime.h>
#include <cstdint>
#include <math.h>

#define MAXN 100000
#define MAXE 800000

// ---------------- device scratch ----------------
__device__ float g_t1[MAXN * 128];
__device__ float g_t2[MAXN * 128];
__device__ float g_h0[MAXN * 128];
__device__ float g_q [MAXN * 128];
__device__ float g_k [MAXN * 128];
__device__ float g_v [MAXN * 128];
__device__ float g_sk[MAXN * 128];
__device__ float g_h1[MAXN * 128];
__device__ float g_wth[9 * 128 * 128];  // transposed weights, tf32 hi part
__device__ float g_wtl[9 * 128 * 128];  // transposed weights, tf32 lo part
__device__ int   g_cnt[MAXN];
__device__ int   g_off[MAXN + 1];
__device__ int   g_bsum[256];
__device__ int   g_pos[MAXE];
__device__ int   g_esrc[MAXE];

__device__ __forceinline__ float to_tf32(float x) {
    float y; asm("cvt.rna.tf32.f32 %0, %1;" : "=f"(y) : "f"(x)); return y;
}

__device__ __forceinline__ void mma_tf32(float c[4], const uint32_t a[4], const uint32_t b[2]) {
    asm volatile(
        "mma.sync.aligned.m16n8k8.row.col.f32.tf32.tf32.f32 "
        "{%0,%1,%2,%3}, {%4,%5,%6,%7}, {%8,%9}, {%0,%1,%2,%3};"
        : "+f"(c[0]), "+f"(c[1]), "+f"(c[2]), "+f"(c[3])
        : "r"(a[0]), "r"(a[1]), "r"(a[2]), "r"(a[3]), "r"(b[0]), "r"(b[1]));
}

// ---- persistent 3xTF32 GEMM: C[M,NOUT] = act(A[M,K] @ Wt^T + bias (+resid)) ----
// Wt hi/lo are [NOUT,K] row-major. B kept resident in SMEM for all tiles.
// 64-row tiles, 256 threads = 8 warps.
template <int K, int NOUT>
__global__ void __launch_bounds__(256, 1)
gemm3x(const float* __restrict__ A,
       const float* __restrict__ Bth, const float* __restrict__ Btl,
       const float* __restrict__ bias, float* __restrict__ C,
       const float* __restrict__ resid, int M, int do_relu)
{
    extern __shared__ float sm[];
    constexpr int LDS_ = K + 4;
    constexpr int K4   = K / 4;
    float* Bh = sm;                         // [NOUT][LDS_]
    float* Bl = Bh + NOUT * LDS_;
    float* Ah = Bl + NOUT * LDS_;           // [64][LDS_]
    float* Al = Ah + 64 * LDS_;

    const int tid  = threadIdx.x;
    const int wid  = tid >> 5;
    const int lane = tid & 31;
    const int g = lane >> 2, t = lane & 3;

    constexpr int WC = NOUT / 32;           // warps along N
    constexpr int WR = 8 / WC;              // warps along M
    constexpr int MT = 64 / (WR * 16);      // 16-row tiles per warp
    constexpr int NT = 4;
    const int wr = wid / WC, wc = wid % WC;
    const int mbase = wr * (MT * 16);
    const int nbase = wc * 32;

    // ---- fill B once (hi+lo) ----
    #pragma unroll
    for (int it = 0; it < (NOUT * K4) / 256; it++) {
        int s = tid + it * 256;
        int r = s / K4, c4 = s % K4;
        float4 vh = ((const float4*)(Bth + (size_t)r * K))[c4];
        float4 vl = ((const float4*)(Btl + (size_t)r * K))[c4];
        *(float4*)(Bh + r * LDS_ + c4 * 4) = vh;
        *(float4*)(Bl + r * LDS_ + c4 * 4) = vl;
    }
    __syncthreads();

    const int ntiles = (M + 63) / 64;
    for (int tile = blockIdx.x; tile < ntiles; tile += gridDim.x) {
        const int m0 = tile * 64;

        // ---- fill A tile (hi/lo split) ----
        #pragma unroll
        for (int it = 0; it < (64 * K4) / 256; it++) {
            int s = tid + it * 256;
            int r = s / K4, c4 = s % K4;
            float4 v;
            if (m0 + r < M) v = ((const float4*)(A + (size_t)(m0 + r) * K))[c4];
            else            v = make_float4(0.f, 0.f, 0.f, 0.f);
            float4 h, l;
            h.x = to_tf32(v.x); l.x = to_tf32(v.x - h.x);
            h.y = to_tf32(v.y); l.y = to_tf32(v.y - h.y);
            h.z = to_tf32(v.z); l.z = to_tf32(v.z - h.z);
            h.w = to_tf32(v.w); l.w = to_tf32(v.w - h.w);
            *(float4*)(Ah + r * LDS_ + c4 * 4) = h;
            *(float4*)(Al + r * LDS_ + c4 * 4) = l;
        }
        __syncthreads();

        float acc[MT][NT][4];
        #pragma unroll
        for (int mt = 0; mt < MT; mt++)
            #pragma unroll
            for (int nt = 0; nt < NT; nt++)
                #pragma unroll
                for (int i = 0; i < 4; i++) acc[mt][nt][i] = 0.f;

        #pragma unroll
        for (int k0 = 0; k0 < K; k0 += 8) {
            uint32_t bh[NT][2], bl[NT][2];
            #pragma unroll
            for (int nt = 0; nt < NT; nt++) {
                int roff = (nbase + nt * 8 + g) * LDS_ + k0 + t;
                bh[nt][0] = __float_as_uint(Bh[roff]);
                bh[nt][1] = __float_as_uint(Bh[roff + 4]);
                bl[nt][0] = __float_as_uint(Bl[roff]);
                bl[nt][1] = __float_as_uint(Bl[roff + 4]);
            }
            #pragma unroll
            for (int mt = 0; mt < MT; mt++) {
                int aoff = (mbase + mt * 16 + g) * LDS_ + k0 + t;
                uint32_t ah[4], al[4];
                ah[0] = __float_as_uint(Ah[aoff]);
                ah[1] = __float_as_uint(Ah[aoff + 8 * LDS_]);
                ah[2] = __float_as_uint(Ah[aoff + 4]);
                ah[3] = __float_as_uint(Ah[aoff + 8 * LDS_ + 4]);
                al[0] = __float_as_uint(Al[aoff]);
                al[1] = __float_as_uint(Al[aoff + 8 * LDS_]);
                al[2] = __float_as_uint(Al[aoff + 4]);
                al[3] = __float_as_uint(Al[aoff + 8 * LDS_ + 4]);
                #pragma unroll
                for (int nt = 0; nt < NT; nt++) {
                    mma_tf32(acc[mt][nt], al, bh[nt]);   // lo*hi
                    mma_tf32(acc[mt][nt], ah, bl[nt]);   // hi*lo
                    mma_tf32(acc[mt][nt], ah, bh[nt]);   // hi*hi
                }
            }
        }
        __syncthreads();   // all reads done before next tile's fill

        // ---- epilogue ----
        #pragma unroll
        for (int mt = 0; mt < MT; mt++) {
            int r0 = m0 + mbase + mt * 16 + g;
            int r1 = r0 + 8;
            #pragma unroll
            for (int nt = 0; nt < NT; nt++) {
                int col = nbase + nt * 8 + 2 * t;
                float2 bv = *(const float2*)(bias + col);
                if (r0 < M) {
                    float2 o;
                    o.x = acc[mt][nt][0] + bv.x;
                    o.y = acc[mt][nt][1] + bv.y;
                    if (resid) {
                        float2 rv = *(const float2*)(resid + (size_t)r0 * NOUT + col);
                        o.x += rv.x; o.y += rv.y;
                    }
                    if (do_relu) { o.x = fmaxf(o.x, 0.f); o.y = fmaxf(o.y, 0.f); }
                    *(float2*)(C + (size_t)r0 * NOUT + col) = o;
                }
                if (r1 < M) {
                    float2 o;
                    o.x = acc[mt][nt][2] + bv.x;
                    o.y = acc[mt][nt][3] + bv.y;
                    if (resid) {
                        float2 rv = *(const float2*)(resid + (size_t)r1 * NOUT + col);
                        o.x += rv.x; o.y += rv.y;
                    }
                    if (do_relu) { o.x = fmaxf(o.x, 0.f); o.y = fmaxf(o.y, 0.f); }
                    *(float2*)(C + (size_t)r1 * NOUT + col) = o;
                }
            }
        }
    }
}

// ---------------- first layer: x[N,5] -> relu(x@W1+b1) [N,64], fp32 exact ----
__global__ void mlp1_kernel(const float* __restrict__ x, const float* __restrict__ W1,
                            const float* __restrict__ b1, float* __restrict__ out, int N)
{
    __shared__ float w[5 * 64];
    __shared__ float b[64];
    int tid = threadIdx.x;
    for (int i = tid; i < 320; i += blockDim.x) w[i] = W1[i];
    if (tid < 64) b[tid] = b1[tid];
    __syncthreads();
    int n = blockIdx.x * blockDim.x + tid;
    if (n >= N) return;
    float xi[5];
    #pragma unroll
    for (int f = 0; f < 5; f++) xi[f] = x[(long)n * 5 + f];
    float* o = out + (long)n * 64;
    #pragma unroll
    for (int j = 0; j < 64; j += 4) {
        float4 v = make_float4(b[j], b[j + 1], b[j + 2], b[j + 3]);
        #pragma unroll
        for (int f = 0; f < 5; f++) {
            float xf = xi[f];
            v.x += xf * w[f * 64 + j + 0];
            v.y += xf * w[f * 64 + j + 1];
            v.z += xf * w[f * 64 + j + 2];
            v.w += xf * w[f * 64 + j + 3];
        }
        v.x = fmaxf(v.x, 0.f); v.y = fmaxf(v.y, 0.f);
        v.z = fmaxf(v.z, 0.f); v.w = fmaxf(v.w, 0.f);
        *(float4*)(o + j) = v;
    }
}

// ---------------- transpose all 9 weight matrices (+tf32 hi/lo split) --------
__global__ void transpose_all(const float* s0, const float* s1, const float* s2,
                              const float* s3, const float* s4, const float* s5,
                              const float* s6, const float* s7, const float* s8)
{
    const int Ks[9] = {64, 128, 128, 128, 128, 128, 128, 64, 128};
    const int Ns[9] = {128, 128, 128, 128, 128, 128, 64, 128, 128};
    const float* srcs[9] = {s0, s1, s2, s3, s4, s5, s6, s7, s8};
    int z = blockIdx.z;
    const float* src = srcs[z];
    float* dh = g_wth + z * 16384;
    float* dl = g_wtl + z * 16384;
    int K = Ks[z], Nc = Ns[z];
    __shared__ float tile[32][33];
    int bx = blockIdx.x * 32, by = blockIdx.y * 32;
    int tx = threadIdx.x, ty = threadIdx.y;
    #pragma unroll
    for (int i = 0; i < 32; i += 8) {
        int k = by + ty + i, n = bx + tx;
        if (k < K && n < Nc) tile[ty + i][tx] = src[(long)k * Nc + n];
    }
    __syncthreads();
    #pragma unroll
    for (int i = 0; i < 32; i += 8) {
        int n = bx + ty + i, k = by + tx;
        if (n < Nc && k < K) {
            float v = tile[tx][ty + i];
            float h = to_tf32(v);
            dh[(long)n * K + k] = h;
            dl[(long)n * K + k] = to_tf32(v - h);
        }
    }
}

// ---------------- CSR build ----------------
__global__ void zero_cnt_kernel(int N)
{
    int i = blockIdx.x * blockDim.x + threadIdx.x;
    if (i < N) g_cnt[i] = 0;
}
__global__ void hist_kernel(const int* __restrict__ dst, int E)
{
    int e = blockIdx.x * blockDim.x + threadIdx.x;
    if (e < E) g_pos[e] = atomicAdd(&g_cnt[dst[e]], 1);
}
__global__ void scan1_kernel(int N)
{
    __shared__ int sh[1024];
    int i = blockIdx.x * 1024 + threadIdx.x;
    int v = (i < N) ? g_cnt[i] : 0;
    sh[threadIdx.x] = v;
    __syncthreads();
    for (int d = 1; d < 1024; d <<= 1) {
        int tmp = (threadIdx.x >= d) ? sh[threadIdx.x - d] : 0;
        __syncthreads();
        sh[threadIdx.x] += tmp;
        __syncthreads();
    }
    if (i < N) g_off[i] = sh[threadIdx.x] - v;
    if (threadIdx.x == 1023) g_bsum[blockIdx.x] = sh[1023];
}
__global__ void scan2_kernel(int nb)
{
    if (blockIdx.x == 0 && threadIdx.x == 0) {
        int run = 0;
        for (int i = 0; i < nb; i++) { int v = g_bsum[i]; g_bsum[i] = run; run += v; }
    }
}
__global__ void scan3_kernel(int N, int E)
{
    int i = blockIdx.x * blockDim.x + threadIdx.x;
    if (i < N) g_off[i] += g_bsum[i >> 10];
    if (i == 0) g_off[N] = E;
}
__global__ void scatter_kernel(const int* __restrict__ src, const int* __restrict__ dst, int E)
{
    int e = blockIdx.x * blockDim.x + threadIdx.x;
    if (e < E) g_esrc[g_off[dst[e]] + g_pos[e]] = src[e];
}

// ---------------- attention: one warp per destination node ----------------
__global__ void attn_kernel(int N)
{
    int gtid = blockIdx.x * blockDim.x + threadIdx.x;
    int n    = gtid >> 5;
    int lane = threadIdx.x & 31;
    if (n >= N) return;

    const float4* q4 = reinterpret_cast<const float4*>(g_q);
    const float4* k4 = reinterpret_cast<const float4*>(g_k);
    const float4* v4 = reinterpret_cast<const float4*>(g_v);
    const float4* s4 = reinterpret_cast<const float4*>(g_sk);
    float4*       o4 = reinterpret_cast<float4*>(g_h1);

    float4 ql = q4[(long)n * 32 + lane];
    int e0 = g_off[n], e1 = g_off[n + 1];

    const float NEG_INF = __int_as_float(0xff800000);
    const float scale = 0.17677669529663687f;  // 1/sqrt(32)
    float m = NEG_INF, s = 0.f;
    float4 acc = make_float4(0.f, 0.f, 0.f, 0.f);

    for (int e = e0; e < e1; e++) {
        int src = g_esrc[e];
        float4 kl = k4[(long)src * 32 + lane];
        float4 vl = v4[(long)src * 32 + lane];
        float p = ql.x * kl.x + ql.y * kl.y + ql.z * kl.z + ql.w * kl.w;
        p += __shfl_xor_sync(0xffffffffu, p, 1);
        p += __shfl_xor_sync(0xffffffffu, p, 2);
        p += __shfl_xor_sync(0xffffffffu, p, 4);
        float c = p * scale;
        float nm = fmaxf(m, c);
        float f = __expf(m - nm);
        float w = __expf(c - nm);
        s = s * f + w;
        acc.x = acc.x * f + w * vl.x;
        acc.y = acc.y * f + w * vl.y;
        acc.z = acc.z * f + w * vl.z;
        acc.w = acc.w * f + w * vl.w;
        m = nm;
    }
    float inv = (s > 0.f) ? (1.f / s) : 0.f;
    float4 sk = s4[(long)n * 32 + lane];
    float4 o;
    o.x = acc.x * inv + sk.x;
    o.y = acc.y * inv + sk.y;
    o.z = acc.z * inv + sk.z;
    o.w = acc.w * inv + sk.w;
    o4[(long)n * 32 + lane] = o;
}

// ---------------- host ----------------
template <int K, int NOUT>
static void launch_gemm3x(const float* A, const float* Bth, const float* Btl,
                          const float* bias, float* C, const float* resid,
                          int M, int relu)
{
    int smem = (2 * NOUT + 2 * 64) * (K + 4) * 4;
    cudaFuncSetAttribute(gemm3x<K, NOUT>, cudaFuncAttributeMaxDynamicSharedMemorySize, smem);
    gemm3x<K, NOUT><<<148, 256, smem>>>(A, Bth, Btl, bias, C, resid, M, relu);
}

extern "C" void kernel_launch(void* const* d_in, const int* in_sizes, int n_in,
                              void* d_out, int out_size)
{
    const float* x    = (const float*)d_in[0];
    const int*   ei   = (const int*)  d_in[1];
    const float* pW1  = (const float*)d_in[2];
    const float* pb1  = (const float*)d_in[3];
    const float* pW2  = (const float*)d_in[4];
    const float* pb2  = (const float*)d_in[5];
    const float* pW3  = (const float*)d_in[6];
    const float* pb3  = (const float*)d_in[7];
    const float* uW1  = (const float*)d_in[8];
    const float* ub1  = (const float*)d_in[9];
    const float* uW2  = (const float*)d_in[10];
    const float* ub2  = (const float*)d_in[11];
    const float* uW3  = (const float*)d_in[12];
    const float* ub3  = (const float*)d_in[13];
    const float* qW   = (const float*)d_in[14];
    const float* qb   = (const float*)d_in[15];
    const float* kW   = (const float*)d_in[16];
    const float* kb   = (const float*)d_in[17];
    const float* vW   = (const float*)d_in[18];
    const float* vb   = (const float*)d_in[19];
    const float* sW   = (const float*)d_in[20];
    const float* sb   = (const float*)d_in[21];
    float* out = (float*)d_out;

    const int F = 5;
    const int N = in_sizes[0] / F;
    const int E = in_sizes[1] / 2;
    const int* src = ei;
    const int* dst = ei + E;

    float *t1, *t2, *h0, *qd, *kd, *vd, *skd, *h1, *wh, *wl;
    cudaGetSymbolAddress((void**)&t1,  g_t1);
    cudaGetSymbolAddress((void**)&t2,  g_t2);
    cudaGetSymbolAddress((void**)&h0,  g_h0);
    cudaGetSymbolAddress((void**)&qd,  g_q);
    cudaGetSymbolAddress((void**)&kd,  g_k);
    cudaGetSymbolAddress((void**)&vd,  g_v);
    cudaGetSymbolAddress((void**)&skd, g_sk);
    cudaGetSymbolAddress((void**)&h1,  g_h1);
    cudaGetSymbolAddress((void**)&wh,  g_wth);
    cudaGetSymbolAddress((void**)&wl,  g_wtl);

    // 0) weight transposes (+ tf32 hi/lo split):
    // z: 0=pW2^T 1=pW3^T 2=qW^T 3=kW^T 4=vW^T 5=sW^T 6=uW1^T 7=uW2^T 8=uW3^T
    {
        dim3 tgrid(4, 4, 9), tblk(32, 8);
        transpose_all<<<tgrid, tblk>>>(pW2, pW3, qW, kW, vW, sW, uW1, uW2, uW3);
    }

    // 1) prep MLP
    mlp1_kernel<<<(N + 255) / 256, 256>>>(x, pW1, pb1, t1, N);
    launch_gemm3x<64, 128>(t1, wh + 0 * 16384, wl + 0 * 16384, pb2, t2, nullptr, N, 1);
    launch_gemm3x<128, 128>(t2, wh + 1 * 16384, wl + 1 * 16384, pb3, h0, nullptr, N, 0);

    // 2) q, k, v, skip projections
    launch_gemm3x<128, 128>(h0, wh + 2 * 16384, wl + 2 * 16384, qb, qd,  nullptr, N, 0);
    launch_gemm3x<128, 128>(h0, wh + 3 * 16384, wl + 3 * 16384, kb, kd,  nullptr, N, 0);
    launch_gemm3x<128, 128>(h0, wh + 4 * 16384, wl + 4 * 16384, vb, vd,  nullptr, N, 0);
    launch_gemm3x<128, 128>(h0, wh + 5 * 16384, wl + 5 * 16384, sb, skd, nullptr, N, 0);

    // 3) CSR build by destination
    int nb1024 = (N + 1023) / 1024;
    zero_cnt_kernel<<<(N + 255) / 256, 256>>>(N);
    hist_kernel<<<(E + 255) / 256, 256>>>(dst, E);
    scan1_kernel<<<nb1024, 1024>>>(N);
    scan2_kernel<<<1, 32>>>(nb1024);
    scan3_kernel<<<(N + 255) / 256, 256>>>(N, E);
    scatter_kernel<<<(E + 255) / 256, 256>>>(src, dst, E);

    // 4) attention -> h1 = agg + skip
    long tt = (long)N * 32;
    attn_kernel<<<(int)((tt + 255) / 256), 256>>>(N);

    // 5) update MLP with residual
    launch_gemm3x<128, 64>(h1, wh + 6 * 16384, wl + 6 * 16384, ub1, t1, nullptr, N, 1);
    launch_gemm3x<64, 128>(t1, wh + 7 * 16384, wl + 7 * 16384, ub2, t2, nullptr, N, 1);
    launch_gemm3x<128, 128>(t2, wh + 8 * 16384, wl + 8 * 16384, ub3, out, h1, N, 0);
}

// round 5
// speedup vs baseline: 1.8632x; 1.2667x over previous
#include <cuda_runtime.h>
#include <cuda_bf16.h>
#include <cstdint>
#include <math.h>

#define MAXN 100000
#define MAXE 800000

// ---------------- device scratch ----------------
__device__ float g_t1[MAXN * 128];
__device__ float g_t2[MAXN * 128];
__device__ float g_h0[MAXN * 128];
__device__ float g_q [MAXN * 128];
__device__ float g_k [MAXN * 128];
__device__ float g_v [MAXN * 128];
__device__ float g_sk[MAXN * 128];
__device__ float g_h1[MAXN * 128];
__device__ __nv_bfloat16 g_wth[9 * 128 * 128];  // transposed weights, bf16 hi
__device__ __nv_bfloat16 g_wtl[9 * 128 * 128];  // transposed weights, bf16 lo
__device__ int   g_cnt[MAXN];
__device__ int   g_off[MAXN + 1];
__device__ int   g_bsum[256];
__device__ int   g_pos[MAXE];
__device__ int   g_esrc[MAXE];

__device__ __forceinline__ uint32_t pack_bf16(float a, float b) {
    __nv_bfloat16 ha = __float2bfloat16(a);
    __nv_bfloat16 hb = __float2bfloat16(b);
    uint16_t ua = *(uint16_t*)&ha, ub = *(uint16_t*)&hb;
    return (uint32_t)ua | ((uint32_t)ub << 16);
}

__device__ __forceinline__ void mma_bf16(float c[4], const uint32_t a[4], const uint32_t b[2]) {
    asm volatile(
        "mma.sync.aligned.m16n8k16.row.col.f32.bf16.bf16.f32 "
        "{%0,%1,%2,%3}, {%4,%5,%6,%7}, {%8,%9}, {%0,%1,%2,%3};"
        : "+f"(c[0]), "+f"(c[1]), "+f"(c[2]), "+f"(c[3])
        : "r"(a[0]), "r"(a[1]), "r"(a[2]), "r"(a[3]), "r"(b[0]), "r"(b[1]));
}

// ---- persistent 3x-bf16 GEMM: C[M,NOUT] = act(A[M,K] @ Wt^T + bias (+resid)) ----
// Wt hi/lo are [NOUT,K] row-major bf16. B resident in SMEM for all tiles.
// 128-row tiles, 512 threads = 16 warps.
template <int K, int NOUT>
__global__ void __launch_bounds__(512, 1)
gemm3x(const float* __restrict__ A,
       const __nv_bfloat16* __restrict__ Bth, const __nv_bfloat16* __restrict__ Btl,
       const float* __restrict__ bias, float* __restrict__ C,
       const float* __restrict__ resid, int M, int do_relu)
{
    extern __shared__ __nv_bfloat16 sm[];
    constexpr int LDSK = K + 8;               // bf16 elements per row (pad = 8 banks/2)
    constexpr int LDSW = LDSK / 2;            // 32-bit words per row
    constexpr int K4   = K / 4;
    __nv_bfloat16* Bh = sm;                   // [NOUT][LDSK]
    __nv_bfloat16* Bl = Bh + NOUT * LDSK;
    __nv_bfloat16* Ah = Bl + NOUT * LDSK;     // [128][LDSK]
    __nv_bfloat16* Al = Ah + 128 * LDSK;
    uint32_t* Bhw = (uint32_t*)Bh;
    uint32_t* Blw = (uint32_t*)Bl;
    uint32_t* Ahw = (uint32_t*)Ah;
    uint32_t* Alw = (uint32_t*)Al;

    const int tid  = threadIdx.x;
    const int wid  = tid >> 5;
    const int lane = tid & 31;
    const int g = lane >> 2, t = lane & 3;

    constexpr int WC = NOUT / 32;             // warps along N (32 cols each)
    constexpr int WR = 16 / WC;               // warps along M
    constexpr int MT = 128 / (WR * 16);       // 16-row tiles per warp
    constexpr int NT = 4;
    const int wr = wid / WC, wc = wid % WC;
    const int mbase = wr * (MT * 16);
    const int nbase = wc * 32;

    // ---- fill B once (hi+lo), plain bf16 copy with 16B chunks ----
    {
        constexpr int CH = K / 8;             // uint4 chunks per row
        for (int s = tid; s < NOUT * CH; s += 512) {
            int r = s / CH, c = s % CH;
            uint4 vh = ((const uint4*)(Bth + (size_t)r * K))[c];
            uint4 vl = ((const uint4*)(Btl + (size_t)r * K))[c];
            *(uint4*)(Bh + r * LDSK + c * 8) = vh;
            *(uint4*)(Bl + r * LDSK + c * 8) = vl;
        }
    }
    __syncthreads();

    const int ntiles = (M + 127) / 128;
    for (int tile = blockIdx.x; tile < ntiles; tile += gridDim.x) {
        const int m0 = tile * 128;

        // ---- fill A tile (fp32 -> bf16 hi/lo split) ----
        #pragma unroll
        for (int it = 0; it < (128 * K4) / 512; it++) {
            int s = tid + it * 512;
            int r = s / K4, c4 = s % K4;
            float4 v;
            if (m0 + r < M) v = ((const float4*)(A + (size_t)(m0 + r) * K))[c4];
            else            v = make_float4(0.f, 0.f, 0.f, 0.f);
            float hx = __bfloat162float(__float2bfloat16(v.x));
            float hy = __bfloat162float(__float2bfloat16(v.y));
            float hz = __bfloat162float(__float2bfloat16(v.z));
            float hw = __bfloat162float(__float2bfloat16(v.w));
            uint2 ph, pl;
            ph.x = pack_bf16(v.x, v.y);
            ph.y = pack_bf16(v.z, v.w);
            pl.x = pack_bf16(v.x - hx, v.y - hy);
            pl.y = pack_bf16(v.z - hz, v.w - hw);
            *(uint2*)(Ah + r * LDSK + c4 * 4) = ph;
            *(uint2*)(Al + r * LDSK + c4 * 4) = pl;
        }
        __syncthreads();

        float acc[MT][NT][4];
        #pragma unroll
        for (int mt = 0; mt < MT; mt++)
            #pragma unroll
            for (int nt = 0; nt < NT; nt++)
                #pragma unroll
                for (int i = 0; i < 4; i++) acc[mt][nt][i] = 0.f;

        #pragma unroll
        for (int k0 = 0; k0 < K; k0 += 16) {
            const int kw = k0 / 2;
            uint32_t bh[NT][2], bl[NT][2];
            #pragma unroll
            for (int nt = 0; nt < NT; nt++) {
                int off = (nbase + nt * 8 + g) * LDSW + kw + t;
                bh[nt][0] = Bhw[off];
                bh[nt][1] = Bhw[off + 4];
                bl[nt][0] = Blw[off];
                bl[nt][1] = Blw[off + 4];
            }
            #pragma unroll
            for (int mt = 0; mt < MT; mt++) {
                int off = (mbase + mt * 16 + g) * LDSW + kw + t;
                uint32_t ah[4], al[4];
                ah[0] = Ahw[off];
                ah[1] = Ahw[off + 8 * LDSW];
                ah[2] = Ahw[off + 4];
                ah[3] = Ahw[off + 8 * LDSW + 4];
                al[0] = Alw[off];
                al[1] = Alw[off + 8 * LDSW];
                al[2] = Alw[off + 4];
                al[3] = Alw[off + 8 * LDSW + 4];
                #pragma unroll
                for (int nt = 0; nt < NT; nt++) {
                    mma_bf16(acc[mt][nt], al, bh[nt]);   // lo*hi
                    mma_bf16(acc[mt][nt], ah, bl[nt]);   // hi*lo
                    mma_bf16(acc[mt][nt], ah, bh[nt]);   // hi*hi
                }
            }
        }
        __syncthreads();   // reads done before next tile's fill

        // ---- epilogue ----
        #pragma unroll
        for (int mt = 0; mt < MT; mt++) {
            int r0 = m0 + mbase + mt * 16 + g;
            int r1 = r0 + 8;
            #pragma unroll
            for (int nt = 0; nt < NT; nt++) {
                int col = nbase + nt * 8 + 2 * t;
                float2 bv = *(const float2*)(bias + col);
                if (r0 < M) {
                    float2 o;
                    o.x = acc[mt][nt][0] + bv.x;
                    o.y = acc[mt][nt][1] + bv.y;
                    if (resid) {
                        float2 rv = *(const float2*)(resid + (size_t)r0 * NOUT + col);
                        o.x += rv.x; o.y += rv.y;
                    }
                    if (do_relu) { o.x = fmaxf(o.x, 0.f); o.y = fmaxf(o.y, 0.f); }
                    *(float2*)(C + (size_t)r0 * NOUT + col) = o;
                }
                if (r1 < M) {
                    float2 o;
                    o.x = acc[mt][nt][2] + bv.x;
                    o.y = acc[mt][nt][3] + bv.y;
                    if (resid) {
                        float2 rv = *(const float2*)(resid + (size_t)r1 * NOUT + col);
                        o.x += rv.x; o.y += rv.y;
                    }
                    if (do_relu) { o.x = fmaxf(o.x, 0.f); o.y = fmaxf(o.y, 0.f); }
                    *(float2*)(C + (size_t)r1 * NOUT + col) = o;
                }
            }
        }
    }
}

// ---------------- first layer: x[N,5] -> relu(x@W1+b1) [N,64], fp32 exact ----
__global__ void mlp1_kernel(const float* __restrict__ x, const float* __restrict__ W1,
                            const float* __restrict__ b1, float* __restrict__ out, int N)
{
    __shared__ float w[5 * 64];
    __shared__ float b[64];
    int tid = threadIdx.x;
    for (int i = tid; i < 320; i += blockDim.x) w[i] = W1[i];
    if (tid < 64) b[tid] = b1[tid];
    __syncthreads();
    int n = blockIdx.x * blockDim.x + tid;
    if (n >= N) return;
    float xi[5];
    #pragma unroll
    for (int f = 0; f < 5; f++) xi[f] = x[(long)n * 5 + f];
    float* o = out + (long)n * 64;
    #pragma unroll
    for (int j = 0; j < 64; j += 4) {
        float4 v = make_float4(b[j], b[j + 1], b[j + 2], b[j + 3]);
        #pragma unroll
        for (int f = 0; f < 5; f++) {
            float xf = xi[f];
            v.x += xf * w[f * 64 + j + 0];
            v.y += xf * w[f * 64 + j + 1];
            v.z += xf * w[f * 64 + j + 2];
            v.w += xf * w[f * 64 + j + 3];
        }
        v.x = fmaxf(v.x, 0.f); v.y = fmaxf(v.y, 0.f);
        v.z = fmaxf(v.z, 0.f); v.w = fmaxf(v.w, 0.f);
        *(float4*)(o + j) = v;
    }
}

// ---------------- transpose all 9 weight matrices (+bf16 hi/lo split) --------
__global__ void transpose_all(const float* s0, const float* s1, const float* s2,
                              const float* s3, const float* s4, const float* s5,
                              const float* s6, const float* s7, const float* s8)
{
    const int Ks[9] = {64, 128, 128, 128, 128, 128, 128, 64, 128};
    const int Ns[9] = {128, 128, 128, 128, 128, 128, 64, 128, 128};
    const float* srcs[9] = {s0, s1, s2, s3, s4, s5, s6, s7, s8};
    int z = blockIdx.z;
    const float* src = srcs[z];
    __nv_bfloat16* dh = g_wth + z * 16384;
    __nv_bfloat16* dl = g_wtl + z * 16384;
    int K = Ks[z], Nc = Ns[z];
    __shared__ float tile[32][33];
    int bx = blockIdx.x * 32, by = blockIdx.y * 32;
    int tx = threadIdx.x, ty = threadIdx.y;
    #pragma unroll
    for (int i = 0; i < 32; i += 8) {
        int k = by + ty + i, n = bx + tx;
        if (k < K && n < Nc) tile[ty + i][tx] = src[(long)k * Nc + n];
    }
    __syncthreads();
    #pragma unroll
    for (int i = 0; i < 32; i += 8) {
        int n = bx + ty + i, k = by + tx;
        if (n < Nc && k < K) {
            float v = tile[tx][ty + i];
            __nv_bfloat16 h = __float2bfloat16(v);
            dh[(long)n * K + k] = h;
            dl[(long)n * K + k] = __float2bfloat16(v - __bfloat162float(h));
        }
    }
}

// ---------------- CSR build ----------------
__global__ void zero_cnt_kernel(int N)
{
    int i = blockIdx.x * blockDim.x + threadIdx.x;
    if (i < N) g_cnt[i] = 0;
}
__global__ void hist_kernel(const int* __restrict__ dst, int E)
{
    int e = blockIdx.x * blockDim.x + threadIdx.x;
    if (e < E) g_pos[e] = atomicAdd(&g_cnt[dst[e]], 1);
}
__global__ void scan1_kernel(int N)
{
    __shared__ int sh[1024];
    int i = blockIdx.x * 1024 + threadIdx.x;
    int v = (i < N) ? g_cnt[i] : 0;
    sh[threadIdx.x] = v;
    __syncthreads();
    for (int d = 1; d < 1024; d <<= 1) {
        int tmp = (threadIdx.x >= d) ? sh[threadIdx.x - d] : 0;
        __syncthreads();
        sh[threadIdx.x] += tmp;
        __syncthreads();
    }
    if (i < N) g_off[i] = sh[threadIdx.x] - v;
    if (threadIdx.x == 1023) g_bsum[blockIdx.x] = sh[1023];
}
__global__ void scan2_kernel(int nb)
{
    if (blockIdx.x == 0 && threadIdx.x == 0) {
        int run = 0;
        for (int i = 0; i < nb; i++) { int v = g_bsum[i]; g_bsum[i] = run; run += v; }
    }
}
__global__ void scan3_kernel(int N, int E)
{
    int i = blockIdx.x * blockDim.x + threadIdx.x;
    if (i < N) g_off[i] += g_bsum[i >> 10];
    if (i == 0) g_off[N] = E;
}
__global__ void scatter_kernel(const int* __restrict__ src, const int* __restrict__ dst, int E)
{
    int e = blockIdx.x * blockDim.x + threadIdx.x;
    if (e < E) g_esrc[g_off[dst[e]] + g_pos[e]] = src[e];
}

// ---------------- attention: one warp per destination node ----------------
__global__ void attn_kernel(int N)
{
    int gtid = blockIdx.x * blockDim.x + threadIdx.x;
    int n    = gtid >> 5;
    int lane = threadIdx.x & 31;
    if (n >= N) return;

    const float4* q4 = reinterpret_cast<const float4*>(g_q);
    const float4* k4 = reinterpret_cast<const float4*>(g_k);
    const float4* v4 = reinterpret_cast<const float4*>(g_v);
    const float4* s4 = reinterpret_cast<const float4*>(g_sk);
    float4*       o4 = reinterpret_cast<float4*>(g_h1);

    float4 ql = q4[(long)n * 32 + lane];
    int e0 = g_off[n], e1 = g_off[n + 1];

    const float NEG_INF = __int_as_float(0xff800000);
    const float scale = 0.17677669529663687f;  // 1/sqrt(32)
    float m = NEG_INF, s = 0.f;
    float4 acc = make_float4(0.f, 0.f, 0.f, 0.f);

    for (int e = e0; e < e1; e++) {
        int src = g_esrc[e];
        float4 kl = k4[(long)src * 32 + lane];
        float4 vl = v4[(long)src * 32 + lane];
        float p = ql.x * kl.x + ql.y * kl.y + ql.z * kl.z + ql.w * kl.w;
        p += __shfl_xor_sync(0xffffffffu, p, 1);
        p += __shfl_xor_sync(0xffffffffu, p, 2);
        p += __shfl_xor_sync(0xffffffffu, p, 4);
        float c = p * scale;
        float nm = fmaxf(m, c);
        float f = __expf(m - nm);
        float w = __expf(c - nm);
        s = s * f + w;
        acc.x = acc.x * f + w * vl.x;
        acc.y = acc.y * f + w * vl.y;
        acc.z = acc.z * f + w * vl.z;
        acc.w = acc.w * f + w * vl.w;
        m = nm;
    }
    float inv = (s > 0.f) ? (1.f / s) : 0.f;
    float4 sk = s4[(long)n * 32 + lane];
    float4 o;
    o.x = acc.x * inv + sk.x;
    o.y = acc.y * inv + sk.y;
    o.z = acc.z * inv + sk.z;
    o.w = acc.w * inv + sk.w;
    o4[(long)n * 32 + lane] = o;
}

// ---------------- host ----------------
template <int K, int NOUT>
static void launch_gemm3x(const float* A, const __nv_bfloat16* Bth, const __nv_bfloat16* Btl,
                          const float* bias, float* C, const float* resid,
                          int M, int relu)
{
    int smem = (2 * NOUT + 2 * 128) * (K + 8) * 2;
    cudaFuncSetAttribute(gemm3x<K, NOUT>, cudaFuncAttributeMaxDynamicSharedMemorySize, smem);
    gemm3x<K, NOUT><<<148, 512, smem>>>(A, Bth, Btl, bias, C, resid, M, relu);
}

extern "C" void kernel_launch(void* const* d_in, const int* in_sizes, int n_in,
                              void* d_out, int out_size)
{
    const float* x    = (const float*)d_in[0];
    const int*   ei   = (const int*)  d_in[1];
    const float* pW1  = (const float*)d_in[2];
    const float* pb1  = (const float*)d_in[3];
    const float* pW2  = (const float*)d_in[4];
    const float* pb2  = (const float*)d_in[5];
    const float* pW3  = (const float*)d_in[6];
    const float* pb3  = (const float*)d_in[7];
    const float* uW1  = (const float*)d_in[8];
    const float* ub1  = (const float*)d_in[9];
    const float* uW2  = (const float*)d_in[10];
    const float* ub2  = (const float*)d_in[11];
    const float* uW3  = (const float*)d_in[12];
    const float* ub3  = (const float*)d_in[13];
    const float* qW   = (const float*)d_in[14];
    const float* qb   = (const float*)d_in[15];
    const float* kW   = (const float*)d_in[16];
    const float* kb   = (const float*)d_in[17];
    const float* vW   = (const float*)d_in[18];
    const float* vb   = (const float*)d_in[19];
    const float* sW   = (const float*)d_in[20];
    const float* sb   = (const float*)d_in[21];
    float* out = (float*)d_out;

    const int F = 5;
    const int N = in_sizes[0] / F;
    const int E = in_sizes[1] / 2;
    const int* src = ei;
    const int* dst = ei + E;

    float *t1, *t2, *h0, *qd, *kd, *vd, *skd, *h1;
    __nv_bfloat16 *wh, *wl;
    cudaGetSymbolAddress((void**)&t1,  g_t1);
    cudaGetSymbolAddress((void**)&t2,  g_t2);
    cudaGetSymbolAddress((void**)&h0,  g_h0);
    cudaGetSymbolAddress((void**)&qd,  g_q);
    cudaGetSymbolAddress((void**)&kd,  g_k);
    cudaGetSymbolAddress((void**)&vd,  g_v);
    cudaGetSymbolAddress((void**)&skd, g_sk);
    cudaGetSymbolAddress((void**)&h1,  g_h1);
    cudaGetSymbolAddress((void**)&wh,  g_wth);
    cudaGetSymbolAddress((void**)&wl,  g_wtl);

    // 0) weight transposes (+ bf16 hi/lo split)
    {
        dim3 tgrid(4, 4, 9), tblk(32, 8);
        transpose_all<<<tgrid, tblk>>>(pW2, pW3, qW, kW, vW, sW, uW1, uW2, uW3);
    }

    // 1) prep MLP
    mlp1_kernel<<<(N + 255) / 256, 256>>>(x, pW1, pb1, t1, N);
    launch_gemm3x<64, 128>(t1, wh + 0 * 16384, wl + 0 * 16384, pb2, t2, nullptr, N, 1);
    launch_gemm3x<128, 128>(t2, wh + 1 * 16384, wl + 1 * 16384, pb3, h0, nullptr, N, 0);

    // 2) q, k, v, skip projections
    launch_gemm3x<128, 128>(h0, wh + 2 * 16384, wl + 2 * 16384, qb, qd,  nullptr, N, 0);
    launch_gemm3x<128, 128>(h0, wh + 3 * 16384, wl + 3 * 16384, kb, kd,  nullptr, N, 0);
    launch_gemm3x<128, 128>(h0, wh + 4 * 16384, wl + 4 * 16384, vb, vd,  nullptr, N, 0);
    launch_gemm3x<128, 128>(h0, wh + 5 * 16384, wl + 5 * 16384, sb, skd, nullptr, N, 0);

    // 3) CSR build by destination
    int nb1024 = (N + 1023) / 1024;
    zero_cnt_kernel<<<(N + 255) / 256, 256>>>(N);
    hist_kernel<<<(E + 255) / 256, 256>>>(dst, E);
    scan1_kernel<<<nb1024, 1024>>>(N);
    scan2_kernel<<<1, 32>>>(nb1024);
    scan3_kernel<<<(N + 255) / 256, 256>>>(N, E);
    scatter_kernel<<<(E + 255) / 256, 256>>>(src, dst, E);

    // 4) attention -> h1 = agg + skip
    long tt = (long)N * 32;
    attn_kernel<<<(int)((tt + 255) / 256), 256>>>(N);

    // 5) update MLP with residual
    launch_gemm3x<128, 64>(h1, wh + 6 * 16384, wl + 6 * 16384, ub1, t1, nullptr, N, 1);
    launch_gemm3x<64, 128>(t1, wh + 7 * 16384, wl + 7 * 16384, ub2, t2, nullptr, N, 1);
    launch_gemm3x<128, 128>(t2, wh + 8 * 16384, wl + 8 * 16384, ub3, out, h1, N, 0);
}

// round 6
// speedup vs baseline: 2.0413x; 1.0956x over previous
#include <cuda_runtime.h>
#include <cuda_bf16.h>
#include <cstdint>
#include <math.h>

#define MAXN 100000
#define MAXE 800000

// ---------------- device scratch ----------------
__device__ float g_t1[MAXN * 128];
__device__ float g_t2[MAXN * 128];
__device__ float g_h0[MAXN * 128];
__device__ float g_qs[MAXN * 256];   // cols 0-127: q, 128-255: skip
__device__ float g_kv[MAXN * 256];   // cols 0-127: k, 128-255: v
__device__ float g_h1[MAXN * 128];
__device__ __nv_bfloat16 g_wth[9 * 128 * 128];  // transposed weights, bf16 hi
__device__ __nv_bfloat16 g_wtl[9 * 128 * 128];  // transposed weights, bf16 lo
__device__ float g_bcat[512];        // [qb|sb|kb|vb]
__device__ int   g_cnt[MAXN];
__device__ int   g_off[MAXN + 1];
__device__ int   g_bsum[256];
__device__ int   g_pos[MAXE];
__device__ int   g_esrc[MAXE];

__device__ __forceinline__ uint32_t smem_u32(const void* p) {
    uint32_t a;
    asm("{ .reg .u64 t; cvta.to.shared.u64 t, %1; cvt.u32.u64 %0, t; }" : "=r"(a) : "l"(p));
    return a;
}

__device__ __forceinline__ uint32_t pack_bf16(float a, float b) {
    __nv_bfloat16 ha = __float2bfloat16(a);
    __nv_bfloat16 hb = __float2bfloat16(b);
    uint16_t ua = *(uint16_t*)&ha, ub = *(uint16_t*)&hb;
    return (uint32_t)ua | ((uint32_t)ub << 16);
}

__device__ __forceinline__ void mma_bf16(float c[4], const uint32_t a[4], const uint32_t b[2]) {
    asm volatile(
        "mma.sync.aligned.m16n8k16.row.col.f32.bf16.bf16.f32 "
        "{%0,%1,%2,%3}, {%4,%5,%6,%7}, {%8,%9}, {%0,%1,%2,%3};"
        : "+f"(c[0]), "+f"(c[1]), "+f"(c[2]), "+f"(c[3])
        : "r"(a[0]), "r"(a[1]), "r"(a[2]), "r"(a[3]), "r"(b[0]), "r"(b[1]));
}

__device__ __forceinline__ void ldsm_x4(uint32_t* r, uint32_t addr) {
    asm volatile("ldmatrix.sync.aligned.m8n8.x4.shared.b16 {%0,%1,%2,%3}, [%4];"
        : "=r"(r[0]), "=r"(r[1]), "=r"(r[2]), "=r"(r[3]) : "r"(addr));
}

// ---- persistent 3x-bf16 GEMM via ldmatrix: C = act(A @ Wt^T + bias (+resid)) ----
// Wt hi/lo [NOUT,K] row-major bf16, resident in SMEM. 128-row tiles, 512 threads.
template <int K, int NOUT>
__global__ void __launch_bounds__(512, 1)
gemm3x(const float* __restrict__ A,
       const __nv_bfloat16* __restrict__ Bth, const __nv_bfloat16* __restrict__ Btl,
       const float* __restrict__ bias, float* __restrict__ C,
       const float* __restrict__ resid, int M, int do_relu)
{
    extern __shared__ __nv_bfloat16 sm[];
    constexpr int LDSK = K + 8;
    constexpr int K4   = K / 4;
    constexpr uint32_t B_BYTES = NOUT * LDSK * 2;   // one B part
    constexpr uint32_t A_BYTES = 128 * LDSK * 2;    // one A part
    __nv_bfloat16* Bh = sm;
    __nv_bfloat16* Bl = Bh + NOUT * LDSK;
    __nv_bfloat16* Ah = Bl + NOUT * LDSK;
    __nv_bfloat16* Al = Ah + 128 * LDSK;

    const int tid  = threadIdx.x;
    const int wid  = tid >> 5;
    const int lane = tid & 31;
    const int g = lane >> 2, t = lane & 3;

    constexpr int WC = NOUT / 32;
    constexpr int WR = 16 / WC;
    constexpr int MT = 128 / (WR * 16);
    constexpr int NT = 4;
    const int wr = wid / WC, wc = wid % WC;
    const int mbase = wr * (MT * 16);
    const int nbase = wc * 32;

    const uint32_t sbase = smem_u32(sm);

    // ---- per-lane ldmatrix base addresses (k0 = 0) ----
    uint32_t aaddr[MT][2], baddr[2][2];
    {
        int lrow  = lane & 15;
        int lhalf = lane >> 4;                       // 0: k-lo, 1: k-hi
        #pragma unroll
        for (int mt = 0; mt < MT; mt++) {
            uint32_t base = sbase + 2 * B_BYTES +
                            ((mbase + mt * 16 + lrow) * LDSK + 8 * lhalf) * 2;
            aaddr[mt][0] = base;
            aaddr[mt][1] = base + A_BYTES;
        }
        int seg  = lane >> 3;                        // 0..3
        int brow = ((seg >> 1) << 3) + (lane & 7);   // 0-7 then 8-15
        int bk   = (seg & 1) * 8;
        #pragma unroll
        for (int p = 0; p < 2; p++) {
            uint32_t base = sbase + ((nbase + p * 16 + brow) * LDSK + bk) * 2;
            baddr[p][0] = base;
            baddr[p][1] = base + B_BYTES;
        }
    }

    // ---- fill B once (hi+lo) ----
    {
        constexpr int CH = K / 8;
        for (int s = tid; s < NOUT * CH; s += 512) {
            int r = s / CH, c = s % CH;
            uint4 vh = ((const uint4*)(Bth + (size_t)r * K))[c];
            uint4 vl = ((const uint4*)(Btl + (size_t)r * K))[c];
            *(uint4*)(Bh + r * LDSK + c * 8) = vh;
            *(uint4*)(Bl + r * LDSK + c * 8) = vl;
        }
    }
    __syncthreads();

    const int ntiles = (M + 127) / 128;
    for (int tile = blockIdx.x; tile < ntiles; tile += gridDim.x) {
        const int m0 = tile * 128;

        // ---- fill A tile (fp32 -> bf16 hi/lo split) ----
        #pragma unroll
        for (int it = 0; it < (128 * K4) / 512; it++) {
            int s = tid + it * 512;
            int r = s / K4, c4 = s % K4;
            float4 v;
            if (m0 + r < M) v = ((const float4*)(A + (size_t)(m0 + r) * K))[c4];
            else            v = make_float4(0.f, 0.f, 0.f, 0.f);
            float hx = __bfloat162float(__float2bfloat16(v.x));
            float hy = __bfloat162float(__float2bfloat16(v.y));
            float hz = __bfloat162float(__float2bfloat16(v.z));
            float hw = __bfloat162float(__float2bfloat16(v.w));
            uint2 ph, pl;
            ph.x = pack_bf16(v.x, v.y);
            ph.y = pack_bf16(v.z, v.w);
            pl.x = pack_bf16(v.x - hx, v.y - hy);
            pl.y = pack_bf16(v.z - hz, v.w - hw);
            *(uint2*)(Ah + r * LDSK + c4 * 4) = ph;
            *(uint2*)(Al + r * LDSK + c4 * 4) = pl;
        }
        __syncthreads();

        float acc[MT][NT][4];
        #pragma unroll
        for (int mt = 0; mt < MT; mt++)
            #pragma unroll
            for (int nt = 0; nt < NT; nt++)
                #pragma unroll
                for (int i = 0; i < 4; i++) acc[mt][nt][i] = 0.f;

        #pragma unroll
        for (int k0 = 0; k0 < K; k0 += 16) {
            const uint32_t koff = k0 * 2;
            uint32_t bh[2][4], bl[2][4];
            #pragma unroll
            for (int p = 0; p < 2; p++) {
                ldsm_x4(bh[p], baddr[p][0] + koff);
                ldsm_x4(bl[p], baddr[p][1] + koff);
            }
            #pragma unroll
            for (int mt = 0; mt < MT; mt++) {
                uint32_t ah[4], al[4];
                ldsm_x4(ah, aaddr[mt][0] + koff);
                ldsm_x4(al, aaddr[mt][1] + koff);
                #pragma unroll
                for (int nt = 0; nt < NT; nt++) {
                    const uint32_t* bhf = &bh[nt >> 1][(nt & 1) * 2];
                    const uint32_t* blf = &bl[nt >> 1][(nt & 1) * 2];
                    mma_bf16(acc[mt][nt], al, bhf);   // lo*hi
                    mma_bf16(acc[mt][nt], ah, blf);   // hi*lo
                    mma_bf16(acc[mt][nt], ah, bhf);   // hi*hi
                }
            }
        }
        __syncthreads();

        // ---- epilogue ----
        #pragma unroll
        for (int mt = 0; mt < MT; mt++) {
            int r0 = m0 + mbase + mt * 16 + g;
            int r1 = r0 + 8;
            #pragma unroll
            for (int nt = 0; nt < NT; nt++) {
                int col = nbase + nt * 8 + 2 * t;
                float2 bv = *(const float2*)(bias + col);
                if (r0 < M) {
                    float2 o;
                    o.x = acc[mt][nt][0] + bv.x;
                    o.y = acc[mt][nt][1] + bv.y;
                    if (resid) {
                        float2 rv = *(const float2*)(resid + (size_t)r0 * NOUT + col);
                        o.x += rv.x; o.y += rv.y;
                    }
                    if (do_relu) { o.x = fmaxf(o.x, 0.f); o.y = fmaxf(o.y, 0.f); }
                    *(float2*)(C + (size_t)r0 * NOUT + col) = o;
                }
                if (r1 < M) {
                    float2 o;
                    o.x = acc[mt][nt][2] + bv.x;
                    o.y = acc[mt][nt][3] + bv.y;
                    if (resid) {
                        float2 rv = *(const float2*)(resid + (size_t)r1 * NOUT + col);
                        o.x += rv.x; o.y += rv.y;
                    }
                    if (do_relu) { o.x = fmaxf(o.x, 0.f); o.y = fmaxf(o.y, 0.f); }
                    *(float2*)(C + (size_t)r1 * NOUT + col) = o;
                }
            }
        }
    }
}

// ---------------- first layer: x[N,5] -> relu(x@W1+b1) [N,64], fp32 exact ----
__global__ void mlp1_kernel(const float* __restrict__ x, const float* __restrict__ W1,
                            const float* __restrict__ b1, float* __restrict__ out, int N)
{
    __shared__ float w[5 * 64];
    __shared__ float b[64];
    int tid = threadIdx.x;
    for (int i = tid; i < 320; i += blockDim.x) w[i] = W1[i];
    if (tid < 64) b[tid] = b1[tid];
    __syncthreads();
    int n = blockIdx.x * blockDim.x + tid;
    if (n >= N) return;
    float xi[5];
    #pragma unroll
    for (int f = 0; f < 5; f++) xi[f] = x[(long)n * 5 + f];
    float* o = out + (long)n * 64;
    #pragma unroll
    for (int j = 0; j < 64; j += 4) {
        float4 v = make_float4(b[j], b[j + 1], b[j + 2], b[j + 3]);
        #pragma unroll
        for (int f = 0; f < 5; f++) {
            float xf = xi[f];
            v.x += xf * w[f * 64 + j + 0];
            v.y += xf * w[f * 64 + j + 1];
            v.z += xf * w[f * 64 + j + 2];
            v.w += xf * w[f * 64 + j + 3];
        }
        v.x = fmaxf(v.x, 0.f); v.y = fmaxf(v.y, 0.f);
        v.z = fmaxf(v.z, 0.f); v.w = fmaxf(v.w, 0.f);
        *(float4*)(o + j) = v;
    }
}

// ---------------- transpose all 9 weight matrices (+bf16 hi/lo split) --------
// slots: 0=pW2 1=pW3 2=qW 3=sW 4=kW 5=vW 6=uW1 7=uW2 8=uW3  (q|s and k|v adjacent)
__global__ void transpose_all(const float* s0, const float* s1, const float* s2,
                              const float* s3, const float* s4, const float* s5,
                              const float* s6, const float* s7, const float* s8)
{
    const int Ks[9] = {64, 128, 128, 128, 128, 128, 128, 64, 128};
    const int Ns[9] = {128, 128, 128, 128, 128, 128, 64, 128, 128};
    const float* srcs[9] = {s0, s1, s2, s3, s4, s5, s6, s7, s8};
    int z = blockIdx.z;
    const float* src = srcs[z];
    __nv_bfloat16* dh = g_wth + z * 16384;
    __nv_bfloat16* dl = g_wtl + z * 16384;
    int K = Ks[z], Nc = Ns[z];
    __shared__ float tile[32][33];
    int bx = blockIdx.x * 32, by = blockIdx.y * 32;
    int tx = threadIdx.x, ty = threadIdx.y;
    #pragma unroll
    for (int i = 0; i < 32; i += 8) {
        int k = by + ty + i, n = bx + tx;
        if (k < K && n < Nc) tile[ty + i][tx] = src[(long)k * Nc + n];
    }
    __syncthreads();
    #pragma unroll
    for (int i = 0; i < 32; i += 8) {
        int n = bx + ty + i, k = by + tx;
        if (n < Nc && k < K) {
            float v = tile[tx][ty + i];
            __nv_bfloat16 h = __float2bfloat16(v);
            dh[(long)n * K + k] = h;
            dl[(long)n * K + k] = __float2bfloat16(v - __bfloat162float(h));
        }
    }
}

__global__ void concat_bias(const float* qb, const float* sb,
                            const float* kb, const float* vb)
{
    int i = threadIdx.x;
    float v = (i < 128) ? qb[i] : (i < 256) ? sb[i - 128]
            : (i < 384) ? kb[i - 256] : vb[i - 384];
    g_bcat[i] = v;
}

// ---------------- CSR build ----------------
__global__ void zero_cnt_kernel(int N)
{
    int i = blockIdx.x * blockDim.x + threadIdx.x;
    if (i < N) g_cnt[i] = 0;
}
__global__ void hist_kernel(const int* __restrict__ dst, int E)
{
    int e = blockIdx.x * blockDim.x + threadIdx.x;
    if (e < E) g_pos[e] = atomicAdd(&g_cnt[dst[e]], 1);
}
__global__ void scan1_kernel(int N)
{
    __shared__ int sh[1024];
    int i = blockIdx.x * 1024 + threadIdx.x;
    int v = (i < N) ? g_cnt[i] : 0;
    sh[threadIdx.x] = v;
    __syncthreads();
    for (int d = 1; d < 1024; d <<= 1) {
        int tmp = (threadIdx.x >= d) ? sh[threadIdx.x - d] : 0;
        __syncthreads();
        sh[threadIdx.x] += tmp;
        __syncthreads();
    }
    if (i < N) g_off[i] = sh[threadIdx.x] - v;
    if (threadIdx.x == 1023) g_bsum[blockIdx.x] = sh[1023];
}
__global__ void scan2_kernel(int nb)
{
    if (blockIdx.x == 0 && threadIdx.x == 0) {
        int run = 0;
        for (int i = 0; i < nb; i++) { int v = g_bsum[i]; g_bsum[i] = run; run += v; }
    }
}
__global__ void scan3_kernel(int N, int E)
{
    int i = blockIdx.x * blockDim.x + threadIdx.x;
    if (i < N) g_off[i] += g_bsum[i >> 10];
    if (i == 0) g_off[N] = E;
}
__global__ void scatter_kernel(const int* __restrict__ src, const int* __restrict__ dst, int E)
{
    int e = blockIdx.x * blockDim.x + threadIdx.x;
    if (e < E) g_esrc[g_off[dst[e]] + g_pos[e]] = src[e];
}

// ---------------- attention: one warp per destination node ----------------
// qs rows: [q(128) | skip(128)]; kv rows: [k(128) | v(128)] -> 256B contiguous gather
__global__ void attn_kernel(int N)
{
    int gtid = blockIdx.x * blockDim.x + threadIdx.x;
    int n    = gtid >> 5;
    int lane = threadIdx.x & 31;
    if (n >= N) return;

    const float4* qs4 = reinterpret_cast<const float4*>(g_qs);
    const float4* kv4 = reinterpret_cast<const float4*>(g_kv);
    float4*       o4  = reinterpret_cast<float4*>(g_h1);

    float4 ql = qs4[(long)n * 64 + lane];
    int e0 = g_off[n], e1 = g_off[n + 1];

    const float NEG_INF = __int_as_float(0xff800000);
    const float scale = 0.17677669529663687f;  // 1/sqrt(32)
    float m = NEG_INF, s = 0.f;
    float4 acc = make_float4(0.f, 0.f, 0.f, 0.f);

    for (int e = e0; e < e1; e++) {
        int src = g_esrc[e];
        float4 kl = kv4[(long)src * 64 + lane];
        float4 vl = kv4[(long)src * 64 + 32 + lane];
        float p = ql.x * kl.x + ql.y * kl.y + ql.z * kl.z + ql.w * kl.w;
        p += __shfl_xor_sync(0xffffffffu, p, 1);
        p += __shfl_xor_sync(0xffffffffu, p, 2);
        p += __shfl_xor_sync(0xffffffffu, p, 4);
        float c = p * scale;
        float nm = fmaxf(m, c);
        float f = __expf(m - nm);
        float w = __expf(c - nm);
        s = s * f + w;
        acc.x = acc.x * f + w * vl.x;
        acc.y = acc.y * f + w * vl.y;
        acc.z = acc.z * f + w * vl.z;
        acc.w = acc.w * f + w * vl.w;
        m = nm;
    }
    float inv = (s > 0.f) ? (1.f / s) : 0.f;
    float4 sk = qs4[(long)n * 64 + 32 + lane];
    float4 o;
    o.x = acc.x * inv + sk.x;
    o.y = acc.y * inv + sk.y;
    o.z = acc.z * inv + sk.z;
    o.w = acc.w * inv + sk.w;
    o4[(long)n * 32 + lane] = o;
}

// ---------------- host ----------------
template <int K, int NOUT>
static void launch_gemm3x(const float* A, const __nv_bfloat16* Bth, const __nv_bfloat16* Btl,
                          const float* bias, float* C, const float* resid,
                          int M, int relu)
{
    int smem = (2 * NOUT + 2 * 128) * (K + 8) * 2;
    cudaFuncSetAttribute(gemm3x<K, NOUT>, cudaFuncAttributeMaxDynamicSharedMemorySize, smem);
    gemm3x<K, NOUT><<<148, 512, smem>>>(A, Bth, Btl, bias, C, resid, M, relu);
}

extern "C" void kernel_launch(void* const* d_in, const int* in_sizes, int n_in,
                              void* d_out, int out_size)
{
    const float* x    = (const float*)d_in[0];
    const int*   ei   = (const int*)  d_in[1];
    const float* pW1  = (const float*)d_in[2];
    const float* pb1  = (const float*)d_in[3];
    const float* pW2  = (const float*)d_in[4];
    const float* pb2  = (const float*)d_in[5];
    const float* pW3  = (const float*)d_in[6];
    const float* pb3  = (const float*)d_in[7];
    const float* uW1  = (const float*)d_in[8];
    const float* ub1  = (const float*)d_in[9];
    const float* uW2  = (const float*)d_in[10];
    const float* ub2  = (const float*)d_in[11];
    const float* uW3  = (const float*)d_in[12];
    const float* ub3  = (const float*)d_in[13];
    const float* qW   = (const float*)d_in[14];
    const float* qb   = (const float*)d_in[15];
    const float* kW   = (const float*)d_in[16];
    const float* kb   = (const float*)d_in[17];
    const float* vW   = (const float*)d_in[18];
    const float* vb   = (const float*)d_in[19];
    const float* sW   = (const float*)d_in[20];
    const float* sb   = (const float*)d_in[21];
    float* out = (float*)d_out;

    const int F = 5;
    const int N = in_sizes[0] / F;
    const int E = in_sizes[1] / 2;
    const int* src = ei;
    const int* dst = ei + E;

    float *t1, *t2, *h0, *qs, *kv, *h1, *bc;
    __nv_bfloat16 *wh, *wl;
    cudaGetSymbolAddress((void**)&t1, g_t1);
    cudaGetSymbolAddress((void**)&t2, g_t2);
    cudaGetSymbolAddress((void**)&h0, g_h0);
    cudaGetSymbolAddress((void**)&qs, g_qs);
    cudaGetSymbolAddress((void**)&kv, g_kv);
    cudaGetSymbolAddress((void**)&h1, g_h1);
    cudaGetSymbolAddress((void**)&bc, g_bcat);
    cudaGetSymbolAddress((void**)&wh, g_wth);
    cudaGetSymbolAddress((void**)&wl, g_wtl);

    // 0) weight transposes (+ bf16 hi/lo split) and bias concat
    {
        dim3 tgrid(4, 4, 9), tblk(32, 8);
        transpose_all<<<tgrid, tblk>>>(pW2, pW3, qW, sW, kW, vW, uW1, uW2, uW3);
        concat_bias<<<1, 512>>>(qb, sb, kb, vb);
    }

    // 1) prep MLP
    mlp1_kernel<<<(N + 255) / 256, 256>>>(x, pW1, pb1, t1, N);
    launch_gemm3x<64, 128>(t1, wh + 0 * 16384, wl + 0 * 16384, pb2, t2, nullptr, N, 1);
    launch_gemm3x<128, 128>(t2, wh + 1 * 16384, wl + 1 * 16384, pb3, h0, nullptr, N, 0);

    // 2) fused projections: [q|skip] and [k|v]
    launch_gemm3x<128, 256>(h0, wh + 2 * 16384, wl + 2 * 16384, bc,       qs, nullptr, N, 0);
    launch_gemm3x<128, 256>(h0, wh + 4 * 16384, wl + 4 * 16384, bc + 256, kv, nullptr, N, 0);

    // 3) CSR build by destination
    int nb1024 = (N + 1023) / 1024;
    zero_cnt_kernel<<<(N + 255) / 256, 256>>>(N);
    hist_kernel<<<(E + 255) / 256, 256>>>(dst, E);
    scan1_kernel<<<nb1024, 1024>>>(N);
    scan2_kernel<<<1, 32>>>(nb1024);
    scan3_kernel<<<(N + 255) / 256, 256>>>(N, E);
    scatter_kernel<<<(E + 255) / 256, 256>>>(src, dst, E);

    // 4) attention -> h1 = agg + skip
    long tt = (long)N * 32;
    attn_kernel<<<(int)((tt + 255) / 256), 256>>>(N);

    // 5) update MLP with residual
    launch_gemm3x<128, 64>(h1, wh + 6 * 16384, wl + 6 * 16384, ub1, t1, nullptr, N, 1);
    launch_gemm3x<64, 128>(t1, wh + 7 * 16384, wl + 7 * 16384, ub2, t2, nullptr, N, 1);
    launch_gemm3x<128, 128>(t2, wh + 8 * 16384, wl + 8 * 16384, ub3, out, h1, N, 0);
}